// round 1
// baseline (speedup 1.0000x reference)
#include <cuda_runtime.h>
#include <math.h>

#define NNODES 4096
#define INC    128
#define HIDC   512
#define OUTC   64
#define NLAYERS 8

// ---------------- scratch (device globals; no allocation allowed) ----------------
__device__ float g_h [NNODES * HIDC];
__device__ float g_t1[NNODES * HIDC];
__device__ float g_t2[NNODES * HIDC];
__device__ float g_L0[NNODES * HIDC];
__device__ float g_Sp[NNODES];
__device__ float g_acc[2];   // [0]=dot(snl@h, h), [1]=||h||^2

// ---------------- small kernels ----------------
__global__ void sp_kernel(const float* __restrict__ S,
                          const float* __restrict__ shift,
                          const float* __restrict__ expo,
                          float* __restrict__ Sp) {
    int i = blockIdx.x * blockDim.x + threadIdx.x;
    if (i < NNODES) Sp[i] = powf(shift[0] + S[i], expo[0]);
}

__global__ void zero_acc_kernel(float* acc) {
    if (threadIdx.x < 2) acc[threadIdx.x] = 0.0f;
}

__global__ void energy_fin_kernel(const float* __restrict__ acc, float* __restrict__ dst) {
    dst[0] = 0.5f * acc[0] / acc[1];
}

// ---------------- SGEMM ----------------
// C[M,N] = epilogue( A[M,K] * B )
// TB=0: B row-major [K,N] (NN)      TB=1: B row-major [N,K] -> C = A*B^T (NT)
// EPI: 0 plain | 1 rowScale | 2 +bias | 3 leaky(+bias) | 4 heun h-update | 5 energy reduce
// M is always 4096 here (multiple of 128); K always multiple of 8; N multiple of 4.
template<int TB, int EPI>
__global__ __launch_bounds__(256)
void sgemm_kernel(int M, int N, int K,
                  const float* __restrict__ A,
                  const float* __restrict__ B,
                  float* __restrict__ C,
                  const float* __restrict__ rowScale,
                  const float* __restrict__ bias,
                  const float* __restrict__ Hin,
                  const float* __restrict__ Lm,
                  const float* __restrict__ ssp,
                  float* __restrict__ acc2)
{
    __shared__ float As[8][132];
    __shared__ float Bs[8][132];

    const int tid = threadIdx.x;
    const int tx = tid & 15;           // 16 threads along N
    const int ty = tid >> 4;           // 16 threads along M
    const int row0 = blockIdx.y * 128 + ty * 8;
    const int col0 = blockIdx.x * 128 + tx * 8;

    // A tile load mapping: 128 rows x 8 cols, one float4 per thread
    const int arow = tid >> 1;
    const int acol = (tid & 1) * 4;
    // B tile (NN): 8 rows x 128 cols
    const int b0row = tid >> 5;
    const int b0col = (tid & 31) * 4;
    // B tile (NT): 128 n-rows x 8 k-cols
    const int b1row = tid >> 1;
    const int b1col = (tid & 1) * 4;

    float acc[8][8];
#pragma unroll
    for (int i = 0; i < 8; i++)
#pragma unroll
        for (int j = 0; j < 8; j++) acc[i][j] = 0.0f;

    const int abase = blockIdx.y * 128;

    for (int k0 = 0; k0 < K; k0 += 8) {
        // ---- load A tile (M=4096 -> always in-bounds) ----
        float4 av = *reinterpret_cast<const float4*>(&A[(size_t)(abase + arow) * K + k0 + acol]);
        As[acol + 0][arow] = av.x;
        As[acol + 1][arow] = av.y;
        As[acol + 2][arow] = av.z;
        As[acol + 3][arow] = av.w;

        // ---- load B tile ----
        if (TB == 0) {
            int col = blockIdx.x * 128 + b0col;
            float4 bv = make_float4(0.f, 0.f, 0.f, 0.f);
            if (col < N)
                bv = *reinterpret_cast<const float4*>(&B[(size_t)(k0 + b0row) * N + col]);
            *reinterpret_cast<float4*>(&Bs[b0row][b0col]) = bv;
        } else {
            int brow = blockIdx.x * 128 + b1row;
            float4 bv = make_float4(0.f, 0.f, 0.f, 0.f);
            if (brow < N)
                bv = *reinterpret_cast<const float4*>(&B[(size_t)brow * K + k0 + b1col]);
            Bs[b1col + 0][b1row] = bv.x;
            Bs[b1col + 1][b1row] = bv.y;
            Bs[b1col + 2][b1row] = bv.z;
            Bs[b1col + 3][b1row] = bv.w;
        }
        __syncthreads();

#pragma unroll
        for (int k = 0; k < 8; k++) {
            float a[8], b[8];
            *reinterpret_cast<float4*>(&a[0]) = *reinterpret_cast<const float4*>(&As[k][ty * 8]);
            *reinterpret_cast<float4*>(&a[4]) = *reinterpret_cast<const float4*>(&As[k][ty * 8 + 4]);
            *reinterpret_cast<float4*>(&b[0]) = *reinterpret_cast<const float4*>(&Bs[k][tx * 8]);
            *reinterpret_cast<float4*>(&b[4]) = *reinterpret_cast<const float4*>(&Bs[k][tx * 8 + 4]);
#pragma unroll
            for (int i = 0; i < 8; i++)
#pragma unroll
                for (int j = 0; j < 8; j++)
                    acc[i][j] += a[i] * b[j];
        }
        __syncthreads();
    }

    // ---- epilogues ----
    if (EPI == 5) {
        // energy reduce: dot += (snl@h)*h ; nrm += h*h . No C store.
        float dot = 0.f, nrm = 0.f;
#pragma unroll
        for (int i = 0; i < 8; i++) {
#pragma unroll
            for (int j = 0; j < 8; j++) {
                int c = col0 + j;
                if (c < N) {
                    float hv = Hin[(size_t)(row0 + i) * N + c];
                    dot += acc[i][j] * hv;
                    nrm += hv * hv;
                }
            }
        }
#pragma unroll
        for (int off = 16; off > 0; off >>= 1) {
            dot += __shfl_down_sync(0xffffffffu, dot, off);
            nrm += __shfl_down_sync(0xffffffffu, nrm, off);
        }
        if ((tid & 31) == 0) {
            atomicAdd(&acc2[0], dot);
            atomicAdd(&acc2[1], nrm);
        }
        return;
    }

    float ss = 0.f, c1 = 0.f, c2 = 0.f;
    if (EPI == 4) {
        ss = ssp[0];
        c1 = -ss;
        c2 = 0.5f * ss * ss;
    }

#pragma unroll
    for (int i = 0; i < 8; i++) {
        int r = row0 + i;
        float rs = (EPI == 1) ? rowScale[r] : 1.0f;
#pragma unroll
        for (int j = 0; j < 8; j++) {
            int c = col0 + j;
            if (c < N) {
                size_t idx = (size_t)r * N + c;
                float v = acc[i][j];
                if (EPI == 0) {
                    C[idx] = v;
                } else if (EPI == 1) {
                    C[idx] = rs * v;
                } else if (EPI == 2) {
                    C[idx] = v + bias[c];
                } else if (EPI == 3) {
                    float t = v + bias[c];
                    C[idx] = (t > 0.f) ? t : 0.01f * t;
                } else if (EPI == 4) {
                    C[idx] = Hin[idx] + c1 * Lm[idx] + c2 * v;
                }
            }
        }
    }
}

// ---------------- launch ----------------
extern "C" void kernel_launch(void* const* d_in, const int* in_sizes, int n_in,
                              void* d_out, int out_size)
{
    (void)in_sizes; (void)n_in;
    const float* x      = (const float*)d_in[0];
    const float* U      = (const float*)d_in[1];
    const float* S      = (const float*)d_in[2];
    const float* Vh     = (const float*)d_in[3];
    const float* snl    = (const float*)d_in[4];
    const float* enc_w  = (const float*)d_in[5];
    const float* enc_b  = (const float*)d_in[6];
    const float* W      = (const float*)d_in[7];
    const float* dec_w0 = (const float*)d_in[8];
    const float* dec_b0 = (const float*)d_in[9];
    const float* dec_w1 = (const float*)d_in[10];
    const float* dec_b1 = (const float*)d_in[11];
    const float* shiftp = (const float*)d_in[12];
    const float* expop  = (const float*)d_in[13];
    const float* ssp    = (const float*)d_in[14];

    float* out  = (float*)d_out;
    float* eout = out + (out_size - (NLAYERS + 1));   // energies tail (9 floats)

    float *ph, *pt1, *pt2, *pL0, *pSp, *pacc;
    cudaGetSymbolAddress((void**)&ph,  g_h);
    cudaGetSymbolAddress((void**)&pt1, g_t1);
    cudaGetSymbolAddress((void**)&pt2, g_t2);
    cudaGetSymbolAddress((void**)&pL0, g_L0);
    cudaGetSymbolAddress((void**)&pSp, g_Sp);
    cudaGetSymbolAddress((void**)&pacc, g_acc);

    dim3 blk(256);
    dim3 gBig((HIDC + 127) / 128, NNODES / 128);   // N=512 -> (4,32)
    dim3 gOut((OUTC + 127) / 128, NNODES / 128);   // N=64  -> (1,32)

    // Sp = (shift + S)^exponent
    sp_kernel<<<(NNODES + 255) / 256, 256>>>(S, shiftp, expop, pSp);

    // encoder: h = x @ enc_w^T + enc_b
    sgemm_kernel<1, 2><<<gBig, blk>>>(NNODES, HIDC, INC, x, enc_w, ph,
                                      nullptr, enc_b, nullptr, nullptr, nullptr, nullptr);

    // energy(h) -> eout[0]
    zero_acc_kernel<<<1, 32>>>(pacc);
    sgemm_kernel<0, 5><<<gBig, blk>>>(NNODES, HIDC, NNODES, snl, ph, nullptr,
                                      nullptr, nullptr, ph, nullptr, nullptr, pacc);
    energy_fin_kernel<<<1, 1>>>(pacc, eout + 0);

    for (int l = 0; l < NLAYERS; l++) {
        // L0 = U @ ((Sp .* (Vh @ h)) @ W)
        sgemm_kernel<0, 1><<<gBig, blk>>>(NNODES, HIDC, NNODES, Vh, ph, pt1,
                                          pSp, nullptr, nullptr, nullptr, nullptr, nullptr);
        sgemm_kernel<0, 0><<<gBig, blk>>>(NNODES, HIDC, HIDC, pt1, W, pt2,
                                          nullptr, nullptr, nullptr, nullptr, nullptr, nullptr);
        sgemm_kernel<0, 0><<<gBig, blk>>>(NNODES, HIDC, NNODES, U, pt2, pL0,
                                          nullptr, nullptr, nullptr, nullptr, nullptr, nullptr);
        // G = lxw(L0); h = h - ss*L0 + 0.5*ss^2*G  (fused into last GEMM)
        sgemm_kernel<0, 1><<<gBig, blk>>>(NNODES, HIDC, NNODES, Vh, pL0, pt1,
                                          pSp, nullptr, nullptr, nullptr, nullptr, nullptr);
        sgemm_kernel<0, 0><<<gBig, blk>>>(NNODES, HIDC, HIDC, pt1, W, pt2,
                                          nullptr, nullptr, nullptr, nullptr, nullptr, nullptr);
        sgemm_kernel<0, 4><<<gBig, blk>>>(NNODES, HIDC, NNODES, U, pt2, ph,
                                          nullptr, nullptr, ph, pL0, ssp, nullptr);
        // energy(h) -> eout[l+1]
        zero_acc_kernel<<<1, 32>>>(pacc);
        sgemm_kernel<0, 5><<<gBig, blk>>>(NNODES, HIDC, NNODES, snl, ph, nullptr,
                                          nullptr, nullptr, ph, nullptr, nullptr, pacc);
        energy_fin_kernel<<<1, 1>>>(pacc, eout + l + 1);
    }

    // decoder
    sgemm_kernel<1, 3><<<gBig, blk>>>(NNODES, HIDC, HIDC, ph, dec_w0, pt2,
                                      nullptr, dec_b0, nullptr, nullptr, nullptr, nullptr);
    sgemm_kernel<1, 2><<<gOut, blk>>>(NNODES, OUTC, HIDC, pt2, dec_w1, out,
                                      nullptr, dec_b1, nullptr, nullptr, nullptr, nullptr);
}

// round 7
// speedup vs baseline: 5.5930x; 5.5930x over previous
#include <cuda_runtime.h>
#include <cuda_bf16.h>
#include <stdint.h>
#include <math.h>

#define NN   4096
#define HID  512
#define INC  128
#define OUTC 64
#define NLAYERS 8

typedef __nv_bfloat16 bf16;

// ---------------- device scratch ----------------
__device__ __align__(16) bf16 g_U_hi   [NN*NN];
__device__ __align__(16) bf16 g_U_lo   [NN*NN];
__device__ __align__(16) bf16 g_VhST_hi[NN*NN];   // (diag(Sp) Vh)^T, row-major [n,k]
__device__ __align__(16) bf16 g_VhST_lo[NN*NN];
__device__ __align__(16) bf16 g_M_hi   [NN*NN];   // M = U diag(Sp) Vh, row-major
__device__ __align__(16) bf16 g_M_lo   [NN*NN];
__device__ __align__(16) bf16 g_S_hi   [NN*NN];   // snl
__device__ __align__(16) bf16 g_S_lo   [NN*NN];
__device__ __align__(16) bf16 g_hR_hi [NN*HID];
__device__ __align__(16) bf16 g_hR_lo [NN*HID];
__device__ __align__(16) bf16 g_hT_hi [HID*NN];
__device__ __align__(16) bf16 g_hT_lo [HID*NN];
__device__ __align__(16) bf16 g_t1T_hi[HID*NN];
__device__ __align__(16) bf16 g_t1T_lo[HID*NN];
__device__ __align__(16) bf16 g_t2T_hi[HID*NN];
__device__ __align__(16) bf16 g_t2T_lo[HID*NN];
__device__ __align__(16) bf16 g_L0R_hi[NN*HID];
__device__ __align__(16) bf16 g_L0R_lo[NN*HID];
__device__ __align__(16) bf16 g_dR_hi [NN*HID];
__device__ __align__(16) bf16 g_dR_lo [NN*HID];
__device__ __align__(16) bf16 g_x_hi  [NN*INC];
__device__ __align__(16) bf16 g_x_lo  [NN*INC];
__device__ __align__(16) bf16 g_Wt_hi [HID*HID];
__device__ __align__(16) bf16 g_Wt_lo [HID*HID];
__device__ __align__(16) bf16 g_ew_hi [HID*INC];
__device__ __align__(16) bf16 g_ew_lo [HID*INC];
__device__ __align__(16) bf16 g_d0w_hi[HID*HID];
__device__ __align__(16) bf16 g_d0w_lo[HID*HID];
__device__ __align__(16) bf16 g_d1w_hi[OUTC*HID];
__device__ __align__(16) bf16 g_d1w_lo[OUTC*HID];
__device__ float g_hf [NN*HID];
__device__ float g_L0f[NN*HID];
__device__ float g_Sp [NN];
__device__ float g_acc[2];

// ---------------- PTX helpers ----------------
__device__ __forceinline__ uint32_t s2u(const void* p) {
    return (uint32_t)__cvta_generic_to_shared(p);
}
__device__ __forceinline__ void cpa16(uint32_t dst, const void* src) {
    asm volatile("cp.async.cg.shared.global [%0], [%1], 16;" :: "r"(dst), "l"(src) : "memory");
}
__device__ __forceinline__ uint32_t swoff(int row, int col16) {
    return (uint32_t)(row * 128 + ((col16 ^ (row & 7)) << 4));
}
__device__ __forceinline__ void ldm4(uint32_t* r, uint32_t addr) {
    asm volatile("ldmatrix.sync.aligned.m8n8.x4.shared.b16 {%0,%1,%2,%3}, [%4];"
                 : "=r"(r[0]), "=r"(r[1]), "=r"(r[2]), "=r"(r[3]) : "r"(addr));
}
__device__ __forceinline__ void mma16816(float* c, const uint32_t* a, uint32_t b0, uint32_t b1) {
    asm volatile("mma.sync.aligned.m16n8k16.row.col.f32.bf16.bf16.f32 "
                 "{%0,%1,%2,%3}, {%4,%5,%6,%7}, {%8,%9}, {%0,%1,%2,%3};"
                 : "+f"(c[0]), "+f"(c[1]), "+f"(c[2]), "+f"(c[3])
                 : "r"(a[0]), "r"(a[1]), "r"(a[2]), "r"(a[3]), "r"(b0), "r"(b1));
}

// ---------------- small kernels ----------------
__global__ void sp_kernel(const float* __restrict__ S, const float* __restrict__ shift,
                          const float* __restrict__ expo, float* __restrict__ Sp) {
    int i = blockIdx.x * blockDim.x + threadIdx.x;
    if (i < NN) Sp[i] = powf(shift[0] + S[i], expo[0]);
}
__global__ void zero_acc_kernel(float* acc) { if (threadIdx.x < 2) acc[threadIdx.x] = 0.0f; }
__global__ void energy_fin_kernel(const float* __restrict__ acc, float* __restrict__ dst) {
    dst[0] = 0.5f * acc[0] / acc[1];
}

// split f32 -> bf16 hi/lo
__global__ void split_kernel(const float* __restrict__ src, bf16* __restrict__ hi,
                             bf16* __restrict__ lo, int total) {
    int i = (blockIdx.x * blockDim.x + threadIdx.x) * 4;
    if (i >= total) return;
    float4 v = *reinterpret_cast<const float4*>(src + i);
    bf16 h0 = __float2bfloat16(v.x), h1 = __float2bfloat16(v.y);
    bf16 h2 = __float2bfloat16(v.z), h3 = __float2bfloat16(v.w);
    bf16 l0 = __float2bfloat16(v.x - __bfloat162float(h0));
    bf16 l1 = __float2bfloat16(v.y - __bfloat162float(h1));
    bf16 l2 = __float2bfloat16(v.z - __bfloat162float(h2));
    bf16 l3 = __float2bfloat16(v.w - __bfloat162float(h3));
    __nv_bfloat162* ph = reinterpret_cast<__nv_bfloat162*>(hi + i);
    __nv_bfloat162* pl = reinterpret_cast<__nv_bfloat162*>(lo + i);
    ph[0] = __nv_bfloat162(h0, h1); ph[1] = __nv_bfloat162(h2, h3);
    pl[0] = __nv_bfloat162(l0, l1); pl[1] = __nv_bfloat162(l2, l3);
}

// transpose + split with optional row scale: out[c*R + r] = rs[r] * src[r*C + c]
__global__ void tsplit_kernel(const float* __restrict__ src, bf16* __restrict__ hiT,
                              bf16* __restrict__ loT, int R, int C,
                              const float* __restrict__ rs) {
    __shared__ float t[32][33];
    int bx = blockIdx.x * 32, by = blockIdx.y * 32;
    int tx = threadIdx.x & 31, ty4 = (threadIdx.x >> 5) * 4;
#pragma unroll
    for (int i = 0; i < 4; i++) {
        int r = by + ty4 + i;
        float v = src[(size_t)r * C + bx + tx];
        if (rs) v *= rs[r];
        t[ty4 + i][tx] = v;
    }
    __syncthreads();
#pragma unroll
    for (int i = 0; i < 4; i++) {
        float v = t[tx][ty4 + i];
        bf16 h = __float2bfloat16(v);
        bf16 l = __float2bfloat16(v - __bfloat162float(h));
        size_t o = (size_t)(bx + ty4 + i) * R + by + tx;
        hiT[o] = h; loT[o] = l;
    }
}

// ---------------- mma.sync GEMM ----------------
// Per CTA: C[128 x TN] = A[M,K] @ B[Ntot,K]^T, bf16 hi/lo split, fp32 accum, 3-term.
// mode bits: 1=F32 | 2=RM split | 4=TR split(smem bounce, ld NN) | 8=HEUN | 16=BIAS | 32=LEAKY | 64=ENERGY
template<int TN>
__global__ __launch_bounds__(256)
void gemm_ts(int mode, int K, int n,
             const bf16* __restrict__ Ah, const bf16* __restrict__ Al, int lda,
             const bf16* __restrict__ Bh, const bf16* __restrict__ Bl, int ldb,
             float* __restrict__ Cf, bf16* __restrict__ RMh, bf16* __restrict__ RMl,
             bf16* __restrict__ TRh, bf16* __restrict__ TRl,
             const float* __restrict__ bias, const float* __restrict__ Hin,
             const float* __restrict__ Lm, const float* __restrict__ ssp,
             float* __restrict__ acc2)
{
    constexpr int STAGE = 32768 + TN * 256;
    constexpr int BOFF  = 32768;
    constexpr int BOFF2 = 32768 + TN * 128;
    constexpr int NT    = TN / 16;
    constexpr int NP    = TN / 32;
    constexpr int BGR   = TN / 32;

    extern __shared__ uint8_t smem[];
    const uint32_t sb = s2u(smem);

    const int tid  = threadIdx.x;
    const int lane = tid & 31;
    const int wid  = tid >> 5;
    const int wm   = wid & 3;
    const int wn   = wid >> 2;

    const int m0 = blockIdx.y * 128;
    const int n0 = blockIdx.x * TN;
    const int NC = K >> 6;

    const int alane = lane & 15, asel = lane >> 4;
    const int bl7   = ((lane >> 4) << 3) + (lane & 7);
    const int bsel  = (lane >> 3) & 1;
    const int awm   = wm * 32;
    const int bwn   = wn * (TN / 2);

    float acc[2][NT][4];
#pragma unroll
    for (int i = 0; i < 2; i++)
#pragma unroll
        for (int j = 0; j < NT; j++)
#pragma unroll
            for (int q = 0; q < 4; q++) acc[i][j][q] = 0.0f;

    auto load_chunk = [&](int c, uint32_t st) {
        int k0 = c << 6;
#pragma unroll
        for (int i = 0; i < 4; i++) {
            int g = tid + i * 256;
            int row = g >> 3, c16 = g & 7;
            uint32_t off = swoff(row, c16);
            size_t so = (size_t)(m0 + row) * lda + k0 + c16 * 8;
            cpa16(st + off,          Ah + so);
            cpa16(st + 16384u + off, Al + so);
        }
#pragma unroll
        for (int i = 0; i < BGR; i++) {
            int g = tid + i * 256;
            int row = g >> 3, c16 = g & 7;
            uint32_t off = swoff(row, c16);
            size_t so = (size_t)(n0 + row) * ldb + k0 + c16 * 8;
            cpa16(st + BOFF  + off, Bh + so);
            cpa16(st + BOFF2 + off, Bl + so);
        }
        asm volatile("cp.async.commit_group;" ::: "memory");
    };

    load_chunk(0, sb);
    if (NC > 1) load_chunk(1, sb + STAGE);

    for (int c = 0; c < NC; c++) {
        uint32_t st = sb + (uint32_t)(c & 1) * STAGE;
        if (c + 2 <= NC) { asm volatile("cp.async.wait_group 1;" ::: "memory"); }
        else             { asm volatile("cp.async.wait_group 0;" ::: "memory"); }
        __syncthreads();

#pragma unroll
        for (int k16 = 0; k16 < 4; k16++) {
            uint32_t ah[2][4], alr[2][4];
            int c16a = 2 * k16 + asel;
#pragma unroll
            for (int mt = 0; mt < 2; mt++) {
                int row = awm + mt * 16 + alane;
                uint32_t so = swoff(row, c16a);
                ldm4(ah[mt],  st + so);
                ldm4(alr[mt], st + 16384u + so);
            }
#pragma unroll
            for (int np = 0; np < NP; np++) {
                int brow = bwn + np * 16 + bl7;
                uint32_t so = swoff(brow, 2 * k16 + bsel);
                uint32_t bh[4], bl[4];
                ldm4(bh, st + BOFF  + so);
                ldm4(bl, st + BOFF2 + so);
#pragma unroll
                for (int mt = 0; mt < 2; mt++) {
#pragma unroll
                    for (int sub = 0; sub < 2; sub++) {
                        float* cc = acc[mt][np * 2 + sub];
                        mma16816(cc, ah[mt],  bh[2*sub], bh[2*sub+1]);
                        mma16816(cc, ah[mt],  bl[2*sub], bl[2*sub+1]);
                        mma16816(cc, alr[mt], bh[2*sub], bh[2*sub+1]);
                    }
                }
            }
        }
        __syncthreads();
        if (c + 2 < NC) load_chunk(c + 2, st);
    }

    // ---------------- epilogue ----------------
    float hss = 0.f, hc2 = 0.f;
    if (mode & 8) { hss = ssp[0]; hc2 = 0.5f * hss * hss; }
    float dot = 0.f, nrm = 0.f;

    const int tq = lane >> 2, tr = lane & 3;
    float* sf = reinterpret_cast<float*>(smem);
    if (mode & 4) __syncthreads();   // tiles dead; reuse smem for TR staging

#pragma unroll
    for (int mt = 0; mt < 2; mt++) {
#pragma unroll
        for (int nt = 0; nt < NT; nt++) {
#pragma unroll
            for (int half = 0; half < 2; half++) {
                int r = m0 + awm + mt * 16 + tq + half * 8;
                int cc = n0 + bwn + nt * 8 + tr * 2;
                float va = acc[mt][nt][half * 2 + 0];
                float vb = acc[mt][nt][half * 2 + 1];
                if (mode & 16) { va += bias[cc]; vb += bias[cc + 1]; }
                if (mode & 32) {
                    va = (va > 0.f) ? va : 0.01f * va;
                    vb = (vb > 0.f) ? vb : 0.01f * vb;
                }
                if (mode & 8) {
                    float2 hv = *reinterpret_cast<const float2*>(Hin + (size_t)r * n + cc);
                    float2 lv = *reinterpret_cast<const float2*>(Lm  + (size_t)r * n + cc);
                    va = hv.x - hss * lv.x + hc2 * va;
                    vb = hv.y - hss * lv.y + hc2 * vb;
                }
                if (mode & 64) {
                    float2 hv = *reinterpret_cast<const float2*>(Hin + (size_t)r * n + cc);
                    dot += va * hv.x + vb * hv.y;
                    nrm += hv.x * hv.x + hv.y * hv.y;
                }
                if (mode & 1) {
                    *reinterpret_cast<float2*>(Cf + (size_t)r * n + cc) = make_float2(va, vb);
                }
                if (mode & 2) {
                    bf16 ha = __float2bfloat16(va), hb = __float2bfloat16(vb);
                    bf16 la = __float2bfloat16(va - __bfloat162float(ha));
                    bf16 lb = __float2bfloat16(vb - __bfloat162float(hb));
                    *reinterpret_cast<__nv_bfloat162*>(RMh + (size_t)r * n + cc) = __nv_bfloat162(ha, hb);
                    *reinterpret_cast<__nv_bfloat162*>(RMl + (size_t)r * n + cc) = __nv_bfloat162(la, lb);
                }
                if (mode & 4) {
                    int cl = bwn + nt * 8 + tr * 2;
                    int rl = awm + mt * 16 + tq + half * 8;
                    sf[cl * 132 + rl]       = va;
                    sf[(cl + 1) * 132 + rl] = vb;
                }
            }
        }
    }

    if (mode & 64) {
#pragma unroll
        for (int off = 16; off > 0; off >>= 1) {
            dot += __shfl_down_sync(0xffffffffu, dot, off);
            nrm += __shfl_down_sync(0xffffffffu, nrm, off);
        }
        if (lane == 0) { atomicAdd(&acc2[0], dot); atomicAdd(&acc2[1], nrm); }
    }

    if (mode & 4) {
        __syncthreads();
        constexpr int TPR = 256 / TN;
        constexpr int CPT = 128 / TPR;
        int rn  = tid / TPR;
        int c0  = (tid % TPR) * CPT;
        size_t gb = (size_t)(n0 + rn) * NN + m0 + c0;
        const float* sr = sf + rn * 132 + c0;
#pragma unroll
        for (int j = 0; j < CPT; j += 2) {
            float va = sr[j], vb = sr[j + 1];
            bf16 ha = __float2bfloat16(va), hb = __float2bfloat16(vb);
            bf16 la = __float2bfloat16(va - __bfloat162float(ha));
            bf16 lb = __float2bfloat16(vb - __bfloat162float(hb));
            *reinterpret_cast<__nv_bfloat162*>(TRh + gb + j) = __nv_bfloat162(ha, hb);
            *reinterpret_cast<__nv_bfloat162*>(TRl + gb + j) = __nv_bfloat162(la, lb);
        }
    }
}

// ---------------- launch ----------------
#define DSMEM_128 131072
#define DSMEM_64  98304

extern "C" void kernel_launch(void* const* d_in, const int* in_sizes, int n_in,
                              void* d_out, int out_size)
{
    (void)in_sizes; (void)n_in;
    const float* x      = (const float*)d_in[0];
    const float* U      = (const float*)d_in[1];
    const float* S      = (const float*)d_in[2];
    const float* Vh     = (const float*)d_in[3];
    const float* snl    = (const float*)d_in[4];
    const float* enc_w  = (const float*)d_in[5];
    const float* enc_b  = (const float*)d_in[6];
    const float* W      = (const float*)d_in[7];
    const float* dec_w0 = (const float*)d_in[8];
    const float* dec_b0 = (const float*)d_in[9];
    const float* dec_w1 = (const float*)d_in[10];
    const float* dec_b1 = (const float*)d_in[11];
    const float* shiftp = (const float*)d_in[12];
    const float* expop  = (const float*)d_in[13];
    const float* ssp    = (const float*)d_in[14];

    float* out  = (float*)d_out;
    float* eout = out + (out_size - (NLAYERS + 1));

    bf16 *Uh,*Ul,*VTh,*VTl,*Mh,*Ml,*Sh,*Sl;
    bf16 *hRh,*hRl,*hTh,*hTl,*t1Th,*t1Tl,*t2Th,*t2Tl,*L0Rh,*L0Rl,*dRh,*dRl;
    bf16 *xh,*xl,*Wth,*Wtl,*ewh,*ewl,*d0h,*d0l,*d1h,*d1l;
    float *hf,*L0f,*Sp,*acc;
    cudaGetSymbolAddress((void**)&Uh,   g_U_hi);    cudaGetSymbolAddress((void**)&Ul,   g_U_lo);
    cudaGetSymbolAddress((void**)&VTh,  g_VhST_hi); cudaGetSymbolAddress((void**)&VTl,  g_VhST_lo);
    cudaGetSymbolAddress((void**)&Mh,   g_M_hi);    cudaGetSymbolAddress((void**)&Ml,   g_M_lo);
    cudaGetSymbolAddress((void**)&Sh,   g_S_hi);    cudaGetSymbolAddress((void**)&Sl,   g_S_lo);
    cudaGetSymbolAddress((void**)&hRh,  g_hR_hi);   cudaGetSymbolAddress((void**)&hRl,  g_hR_lo);
    cudaGetSymbolAddress((void**)&hTh,  g_hT_hi);   cudaGetSymbolAddress((void**)&hTl,  g_hT_lo);
    cudaGetSymbolAddress((void**)&t1Th, g_t1T_hi);  cudaGetSymbolAddress((void**)&t1Tl, g_t1T_lo);
    cudaGetSymbolAddress((void**)&t2Th, g_t2T_hi);  cudaGetSymbolAddress((void**)&t2Tl, g_t2T_lo);
    cudaGetSymbolAddress((void**)&L0Rh, g_L0R_hi);  cudaGetSymbolAddress((void**)&L0Rl, g_L0R_lo);
    cudaGetSymbolAddress((void**)&dRh,  g_dR_hi);   cudaGetSymbolAddress((void**)&dRl,  g_dR_lo);
    cudaGetSymbolAddress((void**)&xh,   g_x_hi);    cudaGetSymbolAddress((void**)&xl,   g_x_lo);
    cudaGetSymbolAddress((void**)&Wth,  g_Wt_hi);   cudaGetSymbolAddress((void**)&Wtl,  g_Wt_lo);
    cudaGetSymbolAddress((void**)&ewh,  g_ew_hi);   cudaGetSymbolAddress((void**)&ewl,  g_ew_lo);
    cudaGetSymbolAddress((void**)&d0h,  g_d0w_hi);  cudaGetSymbolAddress((void**)&d0l,  g_d0w_lo);
    cudaGetSymbolAddress((void**)&d1h,  g_d1w_hi);  cudaGetSymbolAddress((void**)&d1l,  g_d1w_lo);
    cudaGetSymbolAddress((void**)&hf,  g_hf);  cudaGetSymbolAddress((void**)&L0f, g_L0f);
    cudaGetSymbolAddress((void**)&Sp,  g_Sp);  cudaGetSymbolAddress((void**)&acc, g_acc);

    cudaFuncSetAttribute(gemm_ts<128>, cudaFuncAttributeMaxDynamicSharedMemorySize, DSMEM_128);
    cudaFuncSetAttribute(gemm_ts<64>,  cudaFuncAttributeMaxDynamicSharedMemorySize, DSMEM_64);

    dim3 g512(4, 32), g64(1, 32), gMM(32, 32);

    // ---- conversions ----
    sp_kernel<<<(NN + 255) / 256, 256>>>(S, shiftp, expop, Sp);
    split_kernel<<<(NN*NN/4 + 255)/256, 256>>>(U,   Uh, Ul, NN*NN);
    // VhST[n,k] = Sp[k] * Vh[k,n]  (transpose with row scale)
    tsplit_kernel<<<dim3(NN/32, NN/32), 256>>>(Vh, VTh, VTl, NN, NN, Sp);
    split_kernel<<<(NN*NN/4 + 255)/256, 256>>>(snl, Sh, Sl, NN*NN);
    split_kernel<<<(NN*INC/4 + 255)/256, 256>>>(x,  xh, xl, NN*INC);
    split_kernel<<<(HID*INC/4 + 255)/256, 256>>>(enc_w,  ewh, ewl, HID*INC);
    split_kernel<<<(HID*HID/4 + 255)/256, 256>>>(dec_w0, d0h, d0l, HID*HID);
    split_kernel<<<(OUTC*HID/4 + 255)/256, 256>>>(dec_w1, d1h, d1l, OUTC*HID);
    tsplit_kernel<<<dim3(HID/32, HID/32), 256>>>(W, Wth, Wtl, HID, HID, nullptr);

    // ---- M = U @ (diag(Sp) Vh):  A=U RM, B=VhST [n,k];  out RM split (mode 2), n=NN
    gemm_ts<128><<<gMM, 256, DSMEM_128>>>(2, NN, NN, Uh, Ul, NN, VTh, VTl, NN,
        nullptr, Mh, Ml, nullptr, nullptr, nullptr, nullptr, nullptr, nullptr, nullptr);

    // ---- encoder: h = x @ enc_w^T + b  -> f32 + RM + TR   (mode 23 = 1|2|4|16)
    gemm_ts<128><<<g512, 256, DSMEM_128>>>(23, INC, HID, xh, xl, INC, ewh, ewl, INC,
        hf, hRh, hRl, hTh, hTl, enc_b, nullptr, nullptr, nullptr, nullptr);

    zero_acc_kernel<<<1, 32>>>(acc);
    gemm_ts<128><<<g512, 256, DSMEM_128>>>(64, NN, HID, Sh, Sl, NN, hTh, hTl, NN,
        nullptr, nullptr, nullptr, nullptr, nullptr, nullptr, hf, nullptr, nullptr, acc);
    energy_fin_kernel<<<1, 1>>>(acc, eout + 0);

    for (int l = 0; l < NLAYERS; l++) {
        // t1 = h @ W  -> TR split (mode 4)   [K=512]
        gemm_ts<128><<<g512, 256, DSMEM_128>>>(4, HID, HID, hRh, hRl, HID, Wth, Wtl, HID,
            nullptr, nullptr, nullptr, t1Th, t1Tl, nullptr, nullptr, nullptr, nullptr, nullptr);
        // L0 = M @ t1 -> f32 + RM (mode 3)   [K=4096]
        gemm_ts<128><<<g512, 256, DSMEM_128>>>(3, NN, HID, Mh, Ml, NN, t1Th, t1Tl, NN,
            L0f, L0Rh, L0Rl, nullptr, nullptr, nullptr, nullptr, nullptr, nullptr, nullptr);
        // t2 = L0 @ W -> TR split (mode 4)   [K=512]
        gemm_ts<128><<<g512, 256, DSMEM_128>>>(4, HID, HID, L0Rh, L0Rl, HID, Wth, Wtl, HID,
            nullptr, nullptr, nullptr, t2Th, t2Tl, nullptr, nullptr, nullptr, nullptr, nullptr);
        // h = h - ss*L0 + 0.5 ss^2 (M @ t2) -> f32 + RM + TR (mode 15)   [K=4096]
        gemm_ts<128><<<g512, 256, DSMEM_128>>>(15, NN, HID, Mh, Ml, NN, t2Th, t2Tl, NN,
            hf, hRh, hRl, hTh, hTl, nullptr, hf, L0f, ssp, nullptr);
        // energy(h)
        zero_acc_kernel<<<1, 32>>>(acc);
        gemm_ts<128><<<g512, 256, DSMEM_128>>>(64, NN, HID, Sh, Sl, NN, hTh, hTl, NN,
            nullptr, nullptr, nullptr, nullptr, nullptr, nullptr, hf, nullptr, nullptr, acc);
        energy_fin_kernel<<<1, 1>>>(acc, eout + l + 1);
    }

    // ---- decoder ----
    // d = leaky(h @ dec_w0^T + b0) -> RM split (mode 50 = 2|16|32)
    gemm_ts<128><<<g512, 256, DSMEM_128>>>(50, HID, HID, hRh, hRl, HID, d0h, d0l, HID,
        nullptr, dRh, dRl, nullptr, nullptr, dec_b0, nullptr, nullptr, nullptr, nullptr);
    // out = d @ dec_w1^T + b1  (mode 17 = 1|16)
    gemm_ts<64><<<g64, 256, DSMEM_64>>>(17, HID, OUTC, dRh, dRl, HID, d1h, d1l, HID,
        out, nullptr, nullptr, nullptr, nullptr, dec_b1, nullptr, nullptr, nullptr, nullptr);
}

// round 8
// speedup vs baseline: 5.9051x; 1.0558x over previous
#include <cuda_runtime.h>
#include <cuda_bf16.h>
#include <stdint.h>
#include <math.h>

#define NN   4096
#define HID  512
#define INC  128
#define OUTC 64
#define NLAYERS 8
#define NSLAB (NLAYERS + 1)

typedef __nv_bfloat16 bf16;

// ---------------- device scratch ----------------
__device__ __align__(16) bf16 g_U_hi   [NN*NN];
__device__ __align__(16) bf16 g_U_lo   [NN*NN];
__device__ __align__(16) bf16 g_VhST_hi[NN*NN];   // (diag(Sp) Vh)^T  [n,k]
__device__ __align__(16) bf16 g_VhST_lo[NN*NN];
__device__ __align__(16) bf16 g_M_hi   [NN*NN];   // M = U diag(Sp) Vh
__device__ __align__(16) bf16 g_M_lo   [NN*NN];
__device__ __align__(16) bf16 g_S_hi   [NN*NN];   // snl
__device__ __align__(16) bf16 g_S_lo   [NN*NN];
__device__ __align__(16) bf16 g_hR_hi [NN*HID];
__device__ __align__(16) bf16 g_hR_lo [NN*HID];
__device__ __align__(16) bf16 g_hTall_hi[NSLAB*HID*NN];  // TR slabs of h_0..h_8
__device__ __align__(16) bf16 g_hTall_lo[NSLAB*HID*NN];
__device__ __align__(16) bf16 g_t1T_hi[HID*NN];
__device__ __align__(16) bf16 g_t1T_lo[HID*NN];
__device__ __align__(16) bf16 g_t2T_hi[HID*NN];
__device__ __align__(16) bf16 g_t2T_lo[HID*NN];
__device__ __align__(16) bf16 g_L0R_hi[NN*HID];
__device__ __align__(16) bf16 g_L0R_lo[NN*HID];
__device__ __align__(16) bf16 g_dR_hi [NN*HID];
__device__ __align__(16) bf16 g_dR_lo [NN*HID];
__device__ __align__(16) bf16 g_x_hi  [NN*INC];
__device__ __align__(16) bf16 g_x_lo  [NN*INC];
__device__ __align__(16) bf16 g_Wt_hi [HID*HID];
__device__ __align__(16) bf16 g_Wt_lo [HID*HID];
__device__ __align__(16) bf16 g_ew_hi [HID*INC];
__device__ __align__(16) bf16 g_ew_lo [HID*INC];
__device__ __align__(16) bf16 g_d0w_hi[HID*HID];
__device__ __align__(16) bf16 g_d0w_lo[HID*HID];
__device__ __align__(16) bf16 g_d1w_hi[OUTC*HID];
__device__ __align__(16) bf16 g_d1w_lo[OUTC*HID];
__device__ float g_hfall[NSLAB*NN*HID];           // f32 slabs of h_0..h_8
__device__ float g_L0f[NN*HID];
__device__ float g_Sp [NN];
__device__ float g_acc[2*NSLAB];

// ---------------- PTX helpers ----------------
__device__ __forceinline__ uint32_t s2u(const void* p) {
    return (uint32_t)__cvta_generic_to_shared(p);
}
__device__ __forceinline__ void cpa16(uint32_t dst, const void* src) {
    asm volatile("cp.async.cg.shared.global [%0], [%1], 16;" :: "r"(dst), "l"(src) : "memory");
}
__device__ __forceinline__ uint32_t swoff(int row, int col16) {
    return (uint32_t)(row * 128 + ((col16 ^ (row & 7)) << 4));
}
__device__ __forceinline__ void ldm4(uint32_t* r, uint32_t addr) {
    asm volatile("ldmatrix.sync.aligned.m8n8.x4.shared.b16 {%0,%1,%2,%3}, [%4];"
                 : "=r"(r[0]), "=r"(r[1]), "=r"(r[2]), "=r"(r[3]) : "r"(addr));
}
__device__ __forceinline__ void mma16816(float* c, const uint32_t* a, uint32_t b0, uint32_t b1) {
    asm volatile("mma.sync.aligned.m16n8k16.row.col.f32.bf16.bf16.f32 "
                 "{%0,%1,%2,%3}, {%4,%5,%6,%7}, {%8,%9}, {%0,%1,%2,%3};"
                 : "+f"(c[0]), "+f"(c[1]), "+f"(c[2]), "+f"(c[3])
                 : "r"(a[0]), "r"(a[1]), "r"(a[2]), "r"(a[3]), "r"(b0), "r"(b1));
}

// ---------------- small kernels ----------------
__global__ void sp_kernel(const float* __restrict__ S, const float* __restrict__ shift,
                          const float* __restrict__ expo, float* __restrict__ Sp) {
    int i = blockIdx.x * blockDim.x + threadIdx.x;
    if (i < NN) Sp[i] = powf(shift[0] + S[i], expo[0]);
}
__global__ void zero_acc_kernel(float* acc) { if (threadIdx.x < 2*NSLAB) acc[threadIdx.x] = 0.0f; }
__global__ void energy_fin_kernel(const float* __restrict__ acc, float* __restrict__ dst) {
    int i = threadIdx.x;
    if (i < NSLAB) dst[i] = 0.5f * acc[2*i] / acc[2*i+1];
}

// split f32 -> bf16 hi/lo
__global__ void split_kernel(const float* __restrict__ src, bf16* __restrict__ hi,
                             bf16* __restrict__ lo, int total) {
    int i = (blockIdx.x * blockDim.x + threadIdx.x) * 4;
    if (i >= total) return;
    float4 v = *reinterpret_cast<const float4*>(src + i);
    bf16 h0 = __float2bfloat16(v.x), h1 = __float2bfloat16(v.y);
    bf16 h2 = __float2bfloat16(v.z), h3 = __float2bfloat16(v.w);
    bf16 l0 = __float2bfloat16(v.x - __bfloat162float(h0));
    bf16 l1 = __float2bfloat16(v.y - __bfloat162float(h1));
    bf16 l2 = __float2bfloat16(v.z - __bfloat162float(h2));
    bf16 l3 = __float2bfloat16(v.w - __bfloat162float(h3));
    __nv_bfloat162* ph = reinterpret_cast<__nv_bfloat162*>(hi + i);
    __nv_bfloat162* pl = reinterpret_cast<__nv_bfloat162*>(lo + i);
    ph[0] = __nv_bfloat162(h0, h1); ph[1] = __nv_bfloat162(h2, h3);
    pl[0] = __nv_bfloat162(l0, l1); pl[1] = __nv_bfloat162(l2, l3);
}

// transpose + split with optional row scale: out[c*R + r] = rs[r] * src[r*C + c]
__global__ void tsplit_kernel(const float* __restrict__ src, bf16* __restrict__ hiT,
                              bf16* __restrict__ loT, int R, int C,
                              const float* __restrict__ rs) {
    __shared__ float t[32][33];
    int bx = blockIdx.x * 32, by = blockIdx.y * 32;
    int tx = threadIdx.x & 31, ty4 = (threadIdx.x >> 5) * 4;
#pragma unroll
    for (int i = 0; i < 4; i++) {
        int r = by + ty4 + i;
        float v = src[(size_t)r * C + bx + tx];
        if (rs) v *= rs[r];
        t[ty4 + i][tx] = v;
    }
    __syncthreads();
#pragma unroll
    for (int i = 0; i < 4; i++) {
        float v = t[tx][ty4 + i];
        bf16 h = __float2bfloat16(v);
        bf16 l = __float2bfloat16(v - __bfloat162float(h));
        size_t o = (size_t)(bx + ty4 + i) * R + by + tx;
        hiT[o] = h; loT[o] = l;
    }
}

// ---------------- mma.sync GEMM (3-stage pipeline) ----------------
// Per CTA: C[128 x TN] = A[M,K] @ B[Ntot,K]^T, bf16 hi/lo split, fp32 accum, 3-term.
// mode bits: 1=F32 | 2=RM split | 4=TR split(smem bounce, ld NN) | 8=HEUN | 16=BIAS | 32=LEAKY
//            | 64=ENERGY (Hin = f32 slab base, per-512-column-slab reduction)
template<int TN>
__global__ __launch_bounds__(256)
void gemm_ts(int mode, int K, int n,
             const bf16* __restrict__ Ah, const bf16* __restrict__ Al, int lda,
             const bf16* __restrict__ Bh, const bf16* __restrict__ Bl, int ldb,
             float* __restrict__ Cf, bf16* __restrict__ RMh, bf16* __restrict__ RMl,
             bf16* __restrict__ TRh, bf16* __restrict__ TRl,
             const float* __restrict__ bias, const float* __restrict__ Hin,
             const float* __restrict__ Lm, const float* __restrict__ ssp,
             float* __restrict__ acc2)
{
    constexpr int STAGE = 32768 + TN * 256;
    constexpr int BOFF  = 32768;
    constexpr int BOFF2 = 32768 + TN * 128;
    constexpr int NT    = TN / 16;
    constexpr int NP    = TN / 32;
    constexpr int BGR   = TN / 32;

    extern __shared__ uint8_t smem[];
    const uint32_t sb = s2u(smem);

    const int tid  = threadIdx.x;
    const int lane = tid & 31;
    const int wid  = tid >> 5;
    const int wm   = wid & 3;
    const int wn   = wid >> 2;

    const int m0 = blockIdx.y * 128;
    const int n0 = blockIdx.x * TN;
    const int NC = K >> 6;

    const int alane = lane & 15, asel = lane >> 4;
    const int bl7   = ((lane >> 4) << 3) + (lane & 7);
    const int bsel  = (lane >> 3) & 1;
    const int awm   = wm * 32;
    const int bwn   = wn * (TN / 2);

    float acc[2][NT][4];
#pragma unroll
    for (int i = 0; i < 2; i++)
#pragma unroll
        for (int j = 0; j < NT; j++)
#pragma unroll
            for (int q = 0; q < 4; q++) acc[i][j][q] = 0.0f;

    auto load_chunk = [&](int c) {
        uint32_t st = sb + (uint32_t)(c % 3) * STAGE;
        int k0 = c << 6;
#pragma unroll
        for (int i = 0; i < 4; i++) {
            int g = tid + i * 256;
            int row = g >> 3, c16 = g & 7;
            uint32_t off = swoff(row, c16);
            size_t so = (size_t)(m0 + row) * lda + k0 + c16 * 8;
            cpa16(st + off,          Ah + so);
            cpa16(st + 16384u + off, Al + so);
        }
#pragma unroll
        for (int i = 0; i < BGR; i++) {
            int g = tid + i * 256;
            int row = g >> 3, c16 = g & 7;
            uint32_t off = swoff(row, c16);
            size_t so = (size_t)(n0 + row) * ldb + k0 + c16 * 8;
            cpa16(st + BOFF  + off, Bh + so);
            cpa16(st + BOFF2 + off, Bl + so);
        }
        asm volatile("cp.async.commit_group;" ::: "memory");
    };

    load_chunk(0);
    if (NC > 1) load_chunk(1);
    if (NC > 2) load_chunk(2);

    for (int c = 0; c < NC; c++) {
        uint32_t st = sb + (uint32_t)(c % 3) * STAGE;
        if (c + 3 <= NC)      { asm volatile("cp.async.wait_group 2;" ::: "memory"); }
        else if (c + 2 == NC) { asm volatile("cp.async.wait_group 1;" ::: "memory"); }
        else                  { asm volatile("cp.async.wait_group 0;" ::: "memory"); }
        __syncthreads();

#pragma unroll
        for (int k16 = 0; k16 < 4; k16++) {
            uint32_t ah[2][4], alr[2][4];
            int c16a = 2 * k16 + asel;
#pragma unroll
            for (int mt = 0; mt < 2; mt++) {
                int row = awm + mt * 16 + alane;
                uint32_t so = swoff(row, c16a);
                ldm4(ah[mt],  st + so);
                ldm4(alr[mt], st + 16384u + so);
            }
#pragma unroll
            for (int np = 0; np < NP; np++) {
                int brow = bwn + np * 16 + bl7;
                uint32_t so = swoff(brow, 2 * k16 + bsel);
                uint32_t bh[4], bl[4];
                ldm4(bh, st + BOFF  + so);
                ldm4(bl, st + BOFF2 + so);
#pragma unroll
                for (int mt = 0; mt < 2; mt++) {
#pragma unroll
                    for (int sub = 0; sub < 2; sub++) {
                        float* cc = acc[mt][np * 2 + sub];
                        mma16816(cc, ah[mt],  bh[2*sub], bh[2*sub+1]);
                        mma16816(cc, ah[mt],  bl[2*sub], bl[2*sub+1]);
                        mma16816(cc, alr[mt], bh[2*sub], bh[2*sub+1]);
                    }
                }
            }
        }
        __syncthreads();
        if (c + 3 < NC) load_chunk(c + 3);
    }

    // ---------------- epilogue ----------------
    float hss = 0.f, hc2 = 0.f;
    if (mode & 8) { hss = ssp[0]; hc2 = 0.5f * hss * hss; }
    float dot = 0.f, nrm = 0.f;
    const float* ebase = nullptr;
    if (mode & 64) ebase = Hin + (size_t)((n0 + bwn) >> 9) * ((size_t)NN * HID);

    const int tq = lane >> 2, tr = lane & 3;
    float* sf = reinterpret_cast<float*>(smem);
    if (mode & 4) __syncthreads();   // tiles dead; reuse smem for TR staging

#pragma unroll
    for (int mt = 0; mt < 2; mt++) {
#pragma unroll
        for (int nt = 0; nt < NT; nt++) {
#pragma unroll
            for (int half = 0; half < 2; half++) {
                int r = m0 + awm + mt * 16 + tq + half * 8;
                int cc = n0 + bwn + nt * 8 + tr * 2;
                float va = acc[mt][nt][half * 2 + 0];
                float vb = acc[mt][nt][half * 2 + 1];
                if (mode & 16) { va += bias[cc]; vb += bias[cc + 1]; }
                if (mode & 32) {
                    va = (va > 0.f) ? va : 0.01f * va;
                    vb = (vb > 0.f) ? vb : 0.01f * vb;
                }
                if (mode & 8) {
                    float2 hv = *reinterpret_cast<const float2*>(Hin + (size_t)r * n + cc);
                    float2 lv = *reinterpret_cast<const float2*>(Lm  + (size_t)r * n + cc);
                    va = hv.x - hss * lv.x + hc2 * va;
                    vb = hv.y - hss * lv.y + hc2 * vb;
                }
                if (mode & 64) {
                    float2 hv = *reinterpret_cast<const float2*>(ebase + (size_t)r * HID + (cc & 511));
                    dot += va * hv.x + vb * hv.y;
                    nrm += hv.x * hv.x + hv.y * hv.y;
                }
                if (mode & 1) {
                    *reinterpret_cast<float2*>(Cf + (size_t)r * n + cc) = make_float2(va, vb);
                }
                if (mode & 2) {
                    bf16 ha = __float2bfloat16(va), hb = __float2bfloat16(vb);
                    bf16 la = __float2bfloat16(va - __bfloat162float(ha));
                    bf16 lb = __float2bfloat16(vb - __bfloat162float(hb));
                    *reinterpret_cast<__nv_bfloat162*>(RMh + (size_t)r * n + cc) = __nv_bfloat162(ha, hb);
                    *reinterpret_cast<__nv_bfloat162*>(RMl + (size_t)r * n + cc) = __nv_bfloat162(la, lb);
                }
                if (mode & 4) {
                    int cl = bwn + nt * 8 + tr * 2;
                    int rl = awm + mt * 16 + tq + half * 8;
                    sf[cl * 132 + rl]       = va;
                    sf[(cl + 1) * 132 + rl] = vb;
                }
            }
        }
    }

    if (mode & 64) {
#pragma unroll
        for (int off = 16; off > 0; off >>= 1) {
            dot += __shfl_down_sync(0xffffffffu, dot, off);
            nrm += __shfl_down_sync(0xffffffffu, nrm, off);
        }
        if (lane == 0) {
            int l = (n0 + bwn) >> 9;
            atomicAdd(&acc2[2*l],   dot);
            atomicAdd(&acc2[2*l+1], nrm);
        }
    }

    if (mode & 4) {
        __syncthreads();
        constexpr int TPR = 256 / TN;
        constexpr int CPT = 128 / TPR;
        int rn  = tid / TPR;
        int c0  = (tid % TPR) * CPT;
        size_t gb = (size_t)(n0 + rn) * NN + m0 + c0;
        const float* sr = sf + rn * 132 + c0;
#pragma unroll
        for (int j = 0; j < CPT; j += 2) {
            float va = sr[j], vb = sr[j + 1];
            bf16 ha = __float2bfloat16(va), hb = __float2bfloat16(vb);
            bf16 la = __float2bfloat16(va - __bfloat162float(ha));
            bf16 lb = __float2bfloat16(vb - __bfloat162float(hb));
            *reinterpret_cast<__nv_bfloat162*>(TRh + gb + j) = __nv_bfloat162(ha, hb);
            *reinterpret_cast<__nv_bfloat162*>(TRl + gb + j) = __nv_bfloat162(la, lb);
        }
    }
}

// ---------------- launch ----------------
#define DSMEM_128 196608   // 3 x 64KB
#define DSMEM_64  147456   // 3 x 48KB

extern "C" void kernel_launch(void* const* d_in, const int* in_sizes, int n_in,
                              void* d_out, int out_size)
{
    (void)in_sizes; (void)n_in;
    const float* x      = (const float*)d_in[0];
    const float* U      = (const float*)d_in[1];
    const float* S      = (const float*)d_in[2];
    const float* Vh     = (const float*)d_in[3];
    const float* snl    = (const float*)d_in[4];
    const float* enc_w  = (const float*)d_in[5];
    const float* enc_b  = (const float*)d_in[6];
    const float* W      = (const float*)d_in[7];
    const float* dec_w0 = (const float*)d_in[8];
    const float* dec_b0 = (const float*)d_in[9];
    const float* dec_w1 = (const float*)d_in[10];
    const float* dec_b1 = (const float*)d_in[11];
    const float* shiftp = (const float*)d_in[12];
    const float* expop  = (const float*)d_in[13];
    const float* ssp    = (const float*)d_in[14];

    float* out  = (float*)d_out;
    float* eout = out + (out_size - NSLAB);

    bf16 *Uh,*Ul,*VTh,*VTl,*Mh,*Ml,*Sh,*Sl;
    bf16 *hRh,*hRl,*hTh,*hTl,*t1Th,*t1Tl,*t2Th,*t2Tl,*L0Rh,*L0Rl,*dRh,*dRl;
    bf16 *xh,*xl,*Wth,*Wtl,*ewh,*ewl,*d0h,*d0l,*d1h,*d1l;
    float *hfall,*L0f,*Sp,*acc;
    cudaGetSymbolAddress((void**)&Uh,   g_U_hi);    cudaGetSymbolAddress((void**)&Ul,   g_U_lo);
    cudaGetSymbolAddress((void**)&VTh,  g_VhST_hi); cudaGetSymbolAddress((void**)&VTl,  g_VhST_lo);
    cudaGetSymbolAddress((void**)&Mh,   g_M_hi);    cudaGetSymbolAddress((void**)&Ml,   g_M_lo);
    cudaGetSymbolAddress((void**)&Sh,   g_S_hi);    cudaGetSymbolAddress((void**)&Sl,   g_S_lo);
    cudaGetSymbolAddress((void**)&hRh,  g_hR_hi);   cudaGetSymbolAddress((void**)&hRl,  g_hR_lo);
    cudaGetSymbolAddress((void**)&hTh,  g_hTall_hi);cudaGetSymbolAddress((void**)&hTl,  g_hTall_lo);
    cudaGetSymbolAddress((void**)&t1Th, g_t1T_hi);  cudaGetSymbolAddress((void**)&t1Tl, g_t1T_lo);
    cudaGetSymbolAddress((void**)&t2Th, g_t2T_hi);  cudaGetSymbolAddress((void**)&t2Tl, g_t2T_lo);
    cudaGetSymbolAddress((void**)&L0Rh, g_L0R_hi);  cudaGetSymbolAddress((void**)&L0Rl, g_L0R_lo);
    cudaGetSymbolAddress((void**)&dRh,  g_dR_hi);   cudaGetSymbolAddress((void**)&dRl,  g_dR_lo);
    cudaGetSymbolAddress((void**)&xh,   g_x_hi);    cudaGetSymbolAddress((void**)&xl,   g_x_lo);
    cudaGetSymbolAddress((void**)&Wth,  g_Wt_hi);   cudaGetSymbolAddress((void**)&Wtl,  g_Wt_lo);
    cudaGetSymbolAddress((void**)&ewh,  g_ew_hi);   cudaGetSymbolAddress((void**)&ewl,  g_ew_lo);
    cudaGetSymbolAddress((void**)&d0h,  g_d0w_hi);  cudaGetSymbolAddress((void**)&d0l,  g_d0w_lo);
    cudaGetSymbolAddress((void**)&d1h,  g_d1w_hi);  cudaGetSymbolAddress((void**)&d1l,  g_d1w_lo);
    cudaGetSymbolAddress((void**)&hfall,g_hfall);   cudaGetSymbolAddress((void**)&L0f, g_L0f);
    cudaGetSymbolAddress((void**)&Sp,  g_Sp);  cudaGetSymbolAddress((void**)&acc, g_acc);

    cudaFuncSetAttribute(gemm_ts<128>, cudaFuncAttributeMaxDynamicSharedMemorySize, DSMEM_128);
    cudaFuncSetAttribute(gemm_ts<64>,  cudaFuncAttributeMaxDynamicSharedMemorySize, DSMEM_64);

    dim3 g512(4, 32), g64(1, 32), gMM(32, 32), gE(NSLAB * 4, 32);

    const size_t SLABF = (size_t)NN * HID;      // f32 slab stride
    const size_t SLABT = (size_t)HID * NN;      // TR slab stride

    // ---- conversions ----
    sp_kernel<<<(NN + 255) / 256, 256>>>(S, shiftp, expop, Sp);
    split_kernel<<<(NN*NN/4 + 255)/256, 256>>>(U,   Uh, Ul, NN*NN);
    tsplit_kernel<<<dim3(NN/32, NN/32), 256>>>(Vh, VTh, VTl, NN, NN, Sp);
    split_kernel<<<(NN*NN/4 + 255)/256, 256>>>(snl, Sh, Sl, NN*NN);
    split_kernel<<<(NN*INC/4 + 255)/256, 256>>>(x,  xh, xl, NN*INC);
    split_kernel<<<(HID*INC/4 + 255)/256, 256>>>(enc_w,  ewh, ewl, HID*INC);
    split_kernel<<<(HID*HID/4 + 255)/256, 256>>>(dec_w0, d0h, d0l, HID*HID);
    split_kernel<<<(OUTC*HID/4 + 255)/256, 256>>>(dec_w1, d1h, d1l, OUTC*HID);
    tsplit_kernel<<<dim3(HID/32, HID/32), 256>>>(W, Wth, Wtl, HID, HID, nullptr);
    zero_acc_kernel<<<1, 32>>>(acc);

    // ---- M = U @ (diag(Sp) Vh)  -> RM split (mode 2), n=NN
    gemm_ts<128><<<gMM, 256, DSMEM_128>>>(2, NN, NN, Uh, Ul, NN, VTh, VTl, NN,
        nullptr, Mh, Ml, nullptr, nullptr, nullptr, nullptr, nullptr, nullptr, nullptr);

    // ---- encoder: h0 = x @ enc_w^T + b -> f32 slab0 + RM + TR slab0  (mode 23)
    gemm_ts<128><<<g512, 256, DSMEM_128>>>(23, INC, HID, xh, xl, INC, ewh, ewl, INC,
        hfall, hRh, hRl, hTh, hTl, enc_b, nullptr, nullptr, nullptr, nullptr);

    for (int l = 0; l < NLAYERS; l++) {
        // t1 = h @ W  -> TR (mode 4)   [K=512]
        gemm_ts<128><<<g512, 256, DSMEM_128>>>(4, HID, HID, hRh, hRl, HID, Wth, Wtl, HID,
            nullptr, nullptr, nullptr, t1Th, t1Tl, nullptr, nullptr, nullptr, nullptr, nullptr);
        // L0 = M @ t1 -> f32 + RM (mode 3)   [K=4096]
        gemm_ts<128><<<g512, 256, DSMEM_128>>>(3, NN, HID, Mh, Ml, NN, t1Th, t1Tl, NN,
            L0f, L0Rh, L0Rl, nullptr, nullptr, nullptr, nullptr, nullptr, nullptr, nullptr);
        // t2 = L0 @ W -> TR (mode 4)   [K=512]
        gemm_ts<128><<<g512, 256, DSMEM_128>>>(4, HID, HID, L0Rh, L0Rl, HID, Wth, Wtl, HID,
            nullptr, nullptr, nullptr, t2Th, t2Tl, nullptr, nullptr, nullptr, nullptr, nullptr);
        // h_{l+1} = h_l - ss*L0 + 0.5 ss^2 (M @ t2) -> f32 slab l+1 + RM + TR slab l+1 (mode 15)
        gemm_ts<128><<<g512, 256, DSMEM_128>>>(15, NN, HID, Mh, Ml, NN, t2Th, t2Tl, NN,
            hfall + (size_t)(l+1) * SLABF, hRh, hRl,
            hTh + (size_t)(l+1) * SLABT, hTl + (size_t)(l+1) * SLABT,
            nullptr, hfall + (size_t)l * SLABF, L0f, ssp, nullptr);
    }

    // ---- batched energies: snl @ [h_0^T ... h_8^T]  (N = 9*512 = 4608, mode 64)
    gemm_ts<128><<<gE, 256, DSMEM_128>>>(64, NN, NSLAB * HID, Sh, Sl, NN, hTh, hTl, NN,
        nullptr, nullptr, nullptr, nullptr, nullptr, nullptr, hfall, nullptr, nullptr, acc);
    energy_fin_kernel<<<1, 32>>>(acc, eout);

    // ---- decoder ----
    gemm_ts<128><<<g512, 256, DSMEM_128>>>(50, HID, HID, hRh, hRl, HID, d0h, d0l, HID,
        nullptr, dRh, dRl, nullptr, nullptr, dec_b0, nullptr, nullptr, nullptr, nullptr);
    gemm_ts<64><<<g64, 256, DSMEM_64>>>(17, HID, OUTC, dRh, dRl, HID, d1h, d1l, HID,
        out, nullptr, nullptr, nullptr, nullptr, dec_b1, nullptr, nullptr, nullptr, nullptr);
}